// round 15
// baseline (speedup 1.0000x reference)
#include <cuda_runtime.h>
#include <cstdint>

#define NROWS 1024
#define EMB   256

// Zeros are produced by a cudaMemsetAsync graph node (copy-engine path), NOT
// by the kernel. The kernel touches ONLY same-graph pairs (~33K of 1M):
// Row CTA (bid < NROWS), 128 thr, barrier-free:
//   - bounds [lo,hi): 128-elem window, 1 int4/lane, ballots + popc
//   - compute interior warp-per-j (4 streams, 4-way unroll, coalesced
//     LDG.128, 5-step shfl); lane0 STGs pred=relu(dot+b), mask=1
//     (diagonal skipped — memset already zeroed it)
// Count CTA (bid == NROWS): 32-bin histogram; count = sum h^2 - N.
__global__ __launch_bounds__(128) void distmax_interior(
    const float* __restrict__ xs, const int* __restrict__ batch,
    const float* __restrict__ w, const float* __restrict__ bptr,
    float* __restrict__ out_pred, float* __restrict__ out_mask,
    float* __restrict__ out_count)
{
    const int t    = threadIdx.x;
    const int lane = t & 31;
    const int wid  = t >> 5;
    const int bid  = blockIdx.x;

    // ---- count CTA ----
    if (bid == NROWS) {
        __shared__ int h[32];
        if (t < 32) h[t] = 0;
        __syncthreads();
        #pragma unroll
        for (int k = 0; k < 2; k++) {
            int4 v = reinterpret_cast<const int4*>(batch)[t + k * 128];
            atomicAdd(&h[v.x], 1);
            atomicAdd(&h[v.y], 1);
            atomicAdd(&h[v.z], 1);
            atomicAdd(&h[v.w], 1);
        }
        __syncthreads();
        if (t < 32) {
            int c = h[t] * h[t];
            #pragma unroll
            for (int o = 16; o; o >>= 1) c += __shfl_xor_sync(0xffffffffu, c, o);
            if (t == 0) out_count[0] = (float)(c - NROWS);
        }
        return;
    }

    const int i = bid;

    // ---- prefetch independent loads ----
    int wbase = i - 64;
    if (wbase < 0) wbase = 0;
    wbase &= ~3;
    if (wbase > NROWS - 128) wbase = NROWS - 128;

    const int  bi = batch[i];
    const int4 v  = reinterpret_cast<const int4*>(batch + wbase)[lane];

    const float4* xi4 = reinterpret_cast<const float4*>(xs + (size_t)i * EMB);
    const float4* w4  = reinterpret_cast<const float4*>(w);
    const float4 xi0 = xi4[lane], xi1 = xi4[32 + lane];
    const float4 w0  = w4 [lane], w1  = w4 [32 + lane];
    const float bias = __ldg(bptr);

    // ---- ballot bounds (uniform across each warp) ----
    const int d = i - wbase;
    const unsigned m0 = __ballot_sync(0xffffffffu, v.x == bi);
    const unsigned m1 = __ballot_sync(0xffffffffu, v.y == bi);
    const unsigned m2 = __ballot_sync(0xffffffffu, v.z == bi);
    const unsigned m3 = __ballot_sync(0xffffffffu, v.w == bi);

    int nbefore = 0, nafter = 0;
    {
        const unsigned m[4] = {m0, m1, m2, m3};
        #pragma unroll
        for (int c = 0; c < 4; c++) {
            const int nlt = (d - c + 3) >> 2;
            const int nle = (d >= c) ? (((d - c) >> 2) + 1) : 0;
            const unsigned ltm = (unsigned)((1ull << nlt) - 1ull);
            const unsigned lem = (unsigned)((1ull << nle) - 1ull);
            nbefore += __popc(m[c] & ltm);
            nafter  += __popc(m[c] & ~lem);
        }
    }
    const int lo = i - nbefore;
    const int hi = i + nafter + 1;

    float* __restrict__ prow = out_pred + (size_t)i * NROWS;
    float* __restrict__ mrow = out_mask + (size_t)i * NROWS;

    // ---- compute interior only: warp-per-j, 4 streams, 4-way unroll ----
    for (int jb = lo + wid; jb < hi; jb += 16) {
        const int j0 = jb, j1 = jb + 4, j2 = jb + 8, j3 = jb + 12;
        const bool p1 = (j1 < hi), p2 = (j2 < hi), p3 = (j3 < hi);

        float acc0 = 0.f, acc1 = 0.f, acc2 = 0.f, acc3 = 0.f;
        {
            const float4* xj = reinterpret_cast<const float4*>(xs + (size_t)j0 * EMB);
            const float4 a = xj[lane], b = xj[32 + lane];
            acc0 = fmaf(fmaxf(xi0.x, a.x), w0.x, fmaf(fmaxf(xi0.y, a.y), w0.y,
                   fmaf(fmaxf(xi0.z, a.z), w0.z, fmaf(fmaxf(xi0.w, a.w), w0.w,
                   fmaf(fmaxf(xi1.x, b.x), w1.x, fmaf(fmaxf(xi1.y, b.y), w1.y,
                   fmaf(fmaxf(xi1.z, b.z), w1.z, fmaxf(xi1.w, b.w) * w1.w)))))));
        }
        if (p1) {
            const float4* xj = reinterpret_cast<const float4*>(xs + (size_t)j1 * EMB);
            const float4 a = xj[lane], b = xj[32 + lane];
            acc1 = fmaf(fmaxf(xi0.x, a.x), w0.x, fmaf(fmaxf(xi0.y, a.y), w0.y,
                   fmaf(fmaxf(xi0.z, a.z), w0.z, fmaf(fmaxf(xi0.w, a.w), w0.w,
                   fmaf(fmaxf(xi1.x, b.x), w1.x, fmaf(fmaxf(xi1.y, b.y), w1.y,
                   fmaf(fmaxf(xi1.z, b.z), w1.z, fmaxf(xi1.w, b.w) * w1.w)))))));
        }
        if (p2) {
            const float4* xj = reinterpret_cast<const float4*>(xs + (size_t)j2 * EMB);
            const float4 a = xj[lane], b = xj[32 + lane];
            acc2 = fmaf(fmaxf(xi0.x, a.x), w0.x, fmaf(fmaxf(xi0.y, a.y), w0.y,
                   fmaf(fmaxf(xi0.z, a.z), w0.z, fmaf(fmaxf(xi0.w, a.w), w0.w,
                   fmaf(fmaxf(xi1.x, b.x), w1.x, fmaf(fmaxf(xi1.y, b.y), w1.y,
                   fmaf(fmaxf(xi1.z, b.z), w1.z, fmaxf(xi1.w, b.w) * w1.w)))))));
        }
        if (p3) {
            const float4* xj = reinterpret_cast<const float4*>(xs + (size_t)j3 * EMB);
            const float4 a = xj[lane], b = xj[32 + lane];
            acc3 = fmaf(fmaxf(xi0.x, a.x), w0.x, fmaf(fmaxf(xi0.y, a.y), w0.y,
                   fmaf(fmaxf(xi0.z, a.z), w0.z, fmaf(fmaxf(xi0.w, a.w), w0.w,
                   fmaf(fmaxf(xi1.x, b.x), w1.x, fmaf(fmaxf(xi1.y, b.y), w1.y,
                   fmaf(fmaxf(xi1.z, b.z), w1.z, fmaxf(xi1.w, b.w) * w1.w)))))));
        }

        #pragma unroll
        for (int o = 16; o; o >>= 1) {
            acc0 += __shfl_xor_sync(0xffffffffu, acc0, o);
            acc1 += __shfl_xor_sync(0xffffffffu, acc1, o);
            acc2 += __shfl_xor_sync(0xffffffffu, acc2, o);
            acc3 += __shfl_xor_sync(0xffffffffu, acc3, o);
        }

        if (lane == 0) {
            if (j0 != i) { prow[j0] = fmaxf(acc0 + bias, 0.f); mrow[j0] = 1.f; }
            if (p1 && j1 != i) { prow[j1] = fmaxf(acc1 + bias, 0.f); mrow[j1] = 1.f; }
            if (p2 && j2 != i) { prow[j2] = fmaxf(acc2 + bias, 0.f); mrow[j2] = 1.f; }
            if (p3 && j3 != i) { prow[j3] = fmaxf(acc3 + bias, 0.f); mrow[j3] = 1.f; }
        }
    }
}

extern "C" void kernel_launch(void* const* d_in, const int* in_sizes, int n_in,
                              void* d_out, int out_size)
{
    const float* xs    = (const float*)d_in[0];  // [1024, 256] f32
    const int*   batch = (const int*)d_in[1];    // [1024] int32 (sorted, ids in [0,32))
    const float* w     = (const float*)d_in[2];  // [256] f32
    const float* b     = (const float*)d_in[3];  // [1] f32

    float* out       = (float*)d_out;
    float* out_pred  = out;                              // [1024*1024]
    float* out_mask  = out + (size_t)NROWS * NROWS;      // [1024*1024]
    float* out_count = out + 2 * (size_t)NROWS * NROWS;  // [1]

    // Zero the whole output via a graph memset node (copy-engine path),
    // then compute only the ~3% interior on the SMs.
    cudaMemsetAsync(d_out, 0, (size_t)out_size * sizeof(float), 0);
    distmax_interior<<<NROWS + 1, 128>>>(xs, batch, w, b,
                                         out_pred, out_mask, out_count);
}

// round 16
// speedup vs baseline: 1.3761x; 1.3761x over previous
#include <cuda_runtime.h>
#include <cstdint>

#define NROWS 1024
#define EMB   256

// One CTA (128 thr) per row + 1 count CTA.
// Strategy: TMA-zero the two output rows EARLY from a 4KB shared zero buffer
// (2 cp.async.bulk stores issued right after bounds), overlap the drain with
// the interior compute (kept in registers), then after wait+barrier write the
// ~32 interior pred/mask values with direct STG.32 (diagonal stays zero).
// This removes R13's interior-STS pass, half its smem zeroing, and takes the
// TMA drain off the CTA tail.
// Row CTA:
//   - prefetch xi/w/window/bias; zero 4KB smem (2 STS.128/thr)
//   - ballot bounds [lo,hi) (128-elem window, popc thresholds)
//   - __syncthreads; tid0: fence.proxy.async + 2 bulk zero-stores + commit
//   - compute interior warp-per-j (4 streams, 4-way unroll, coalesced
//     LDG.128, 5-step shfl) into registers
//   - tid0: wait_group 0; __syncthreads; lane0 STGs pred/mask per j
// Count CTA (bid == NROWS): 32-bin histogram; count = sum h^2 - N.
__global__ __launch_bounds__(128) void distmax_all(
    const float* __restrict__ xs, const int* __restrict__ batch,
    const float* __restrict__ w, const float* __restrict__ bptr,
    float* __restrict__ out_pred, float* __restrict__ out_mask,
    float* __restrict__ out_count)
{
    const int t    = threadIdx.x;
    const int lane = t & 31;
    const int wid  = t >> 5;
    const int bid  = blockIdx.x;

    // ---- count CTA ----
    if (bid == NROWS) {
        __shared__ int h[32];
        if (t < 32) h[t] = 0;
        __syncthreads();
        #pragma unroll
        for (int k = 0; k < 2; k++) {
            int4 v = reinterpret_cast<const int4*>(batch)[t + k * 128];
            atomicAdd(&h[v.x], 1);
            atomicAdd(&h[v.y], 1);
            atomicAdd(&h[v.z], 1);
            atomicAdd(&h[v.w], 1);
        }
        __syncthreads();
        if (t < 32) {
            int c = h[t] * h[t];
            #pragma unroll
            for (int o = 16; o; o >>= 1) c += __shfl_xor_sync(0xffffffffu, c, o);
            if (t == 0) out_count[0] = (float)(c - NROWS);
        }
        return;
    }

    __shared__ __align__(16) float s_zero[NROWS];  // 4KB of zeros

    const int i = bid;

    // ---- prefetch independent loads ----
    int wbase = i - 64;
    if (wbase < 0) wbase = 0;
    wbase &= ~3;
    if (wbase > NROWS - 128) wbase = NROWS - 128;

    const int  bi = batch[i];
    const int4 v  = reinterpret_cast<const int4*>(batch + wbase)[lane];

    const float4* xi4 = reinterpret_cast<const float4*>(xs + (size_t)i * EMB);
    const float4* w4  = reinterpret_cast<const float4*>(w);
    const float4 xi0 = xi4[lane], xi1 = xi4[32 + lane];
    const float4 w0  = w4 [lane], w1  = w4 [32 + lane];
    const float bias = __ldg(bptr);

    // ---- zero the 4KB shared buffer: 256 float4 / 128 thr = 2 each ----
    {
        float4* s4 = reinterpret_cast<float4*>(s_zero);
        const float4 z = make_float4(0.f, 0.f, 0.f, 0.f);
        s4[t]       = z;
        s4[t + 128] = z;
    }

    // ---- ballot bounds (uniform across each warp) ----
    const int d = i - wbase;
    const unsigned m0 = __ballot_sync(0xffffffffu, v.x == bi);
    const unsigned m1 = __ballot_sync(0xffffffffu, v.y == bi);
    const unsigned m2 = __ballot_sync(0xffffffffu, v.z == bi);
    const unsigned m3 = __ballot_sync(0xffffffffu, v.w == bi);

    int nbefore = 0, nafter = 0;
    {
        const unsigned m[4] = {m0, m1, m2, m3};
        #pragma unroll
        for (int c = 0; c < 4; c++) {
            const int nlt = (d - c + 3) >> 2;
            const int nle = (d >= c) ? (((d - c) >> 2) + 1) : 0;
            const unsigned ltm = (unsigned)((1ull << nlt) - 1ull);
            const unsigned lem = (unsigned)((1ull << nle) - 1ull);
            nbefore += __popc(m[c] & ltm);
            nafter  += __popc(m[c] & ~lem);
        }
    }
    const int lo = i - nbefore;
    const int hi = i + nafter + 1;

    float* __restrict__ prow = out_pred + (size_t)i * NROWS;
    float* __restrict__ mrow = out_mask + (size_t)i * NROWS;

    // ---- publish smem zeros, then issue the 2 bulk zero-stores EARLY ----
    __syncthreads();
    if (t == 0) {
        asm volatile("fence.proxy.async.shared::cta;" ::: "memory");
        uint32_t saddr = (uint32_t)__cvta_generic_to_shared(s_zero);
        asm volatile("cp.async.bulk.global.shared::cta.bulk_group [%0], [%1], %2;"
                     :: "l"(prow), "r"(saddr), "r"(4096u) : "memory");
        asm volatile("cp.async.bulk.global.shared::cta.bulk_group [%0], [%1], %2;"
                     :: "l"(mrow), "r"(saddr), "r"(4096u) : "memory");
        asm volatile("cp.async.bulk.commit_group;" ::: "memory");
    }

    // ---- compute interior into registers (overlaps the TMA drain) ----
    // 4 streams x 4-way unroll; interior width <= 64 -> at most 1 iteration
    // per stream in the common case.
    const int j0 = lo + wid;
    const int j1 = j0 + 4, j2 = j0 + 8, j3 = j0 + 12;
    // Up to 2 blocks of 16 cover interior width up to 64+; loop for safety.
    for (int jb = j0; jb < hi; jb += 16) {
        const int k0 = jb, k1 = jb + 4, k2 = jb + 8, k3 = jb + 12;
        const bool q1 = (k1 < hi), q2 = (k2 < hi), q3 = (k3 < hi);

        float acc0 = 0.f, acc1 = 0.f, acc2 = 0.f, acc3 = 0.f;
        {
            const float4* xj = reinterpret_cast<const float4*>(xs + (size_t)k0 * EMB);
            const float4 a = xj[lane], b = xj[32 + lane];
            acc0 = fmaf(fmaxf(xi0.x, a.x), w0.x, fmaf(fmaxf(xi0.y, a.y), w0.y,
                   fmaf(fmaxf(xi0.z, a.z), w0.z, fmaf(fmaxf(xi0.w, a.w), w0.w,
                   fmaf(fmaxf(xi1.x, b.x), w1.x, fmaf(fmaxf(xi1.y, b.y), w1.y,
                   fmaf(fmaxf(xi1.z, b.z), w1.z, fmaxf(xi1.w, b.w) * w1.w)))))));
        }
        if (q1) {
            const float4* xj = reinterpret_cast<const float4*>(xs + (size_t)k1 * EMB);
            const float4 a = xj[lane], b = xj[32 + lane];
            acc1 = fmaf(fmaxf(xi0.x, a.x), w0.x, fmaf(fmaxf(xi0.y, a.y), w0.y,
                   fmaf(fmaxf(xi0.z, a.z), w0.z, fmaf(fmaxf(xi0.w, a.w), w0.w,
                   fmaf(fmaxf(xi1.x, b.x), w1.x, fmaf(fmaxf(xi1.y, b.y), w1.y,
                   fmaf(fmaxf(xi1.z, b.z), w1.z, fmaxf(xi1.w, b.w) * w1.w)))))));
        }
        if (q2) {
            const float4* xj = reinterpret_cast<const float4*>(xs + (size_t)k2 * EMB);
            const float4 a = xj[lane], b = xj[32 + lane];
            acc2 = fmaf(fmaxf(xi0.x, a.x), w0.x, fmaf(fmaxf(xi0.y, a.y), w0.y,
                   fmaf(fmaxf(xi0.z, a.z), w0.z, fmaf(fmaxf(xi0.w, a.w), w0.w,
                   fmaf(fmaxf(xi1.x, b.x), w1.x, fmaf(fmaxf(xi1.y, b.y), w1.y,
                   fmaf(fmaxf(xi1.z, b.z), w1.z, fmaxf(xi1.w, b.w) * w1.w)))))));
        }
        if (q3) {
            const float4* xj = reinterpret_cast<const float4*>(xs + (size_t)k3 * EMB);
            const float4 a = xj[lane], b = xj[32 + lane];
            acc3 = fmaf(fmaxf(xi0.x, a.x), w0.x, fmaf(fmaxf(xi0.y, a.y), w0.y,
                   fmaf(fmaxf(xi0.z, a.z), w0.z, fmaf(fmaxf(xi0.w, a.w), w0.w,
                   fmaf(fmaxf(xi1.x, b.x), w1.x, fmaf(fmaxf(xi1.y, b.y), w1.y,
                   fmaf(fmaxf(xi1.z, b.z), w1.z, fmaxf(xi1.w, b.w) * w1.w)))))));
        }

        #pragma unroll
        for (int o = 16; o; o >>= 1) {
            acc0 += __shfl_xor_sync(0xffffffffu, acc0, o);
            acc1 += __shfl_xor_sync(0xffffffffu, acc1, o);
            acc2 += __shfl_xor_sync(0xffffffffu, acc2, o);
            acc3 += __shfl_xor_sync(0xffffffffu, acc3, o);
        }

        // Zeros must land before interior STGs: drain TMA once, then barrier.
        if (jb == j0) {
            if (t == 0) {
                asm volatile("cp.async.bulk.wait_group 0;" ::: "memory");
            }
            __syncthreads();
        }

        if (lane == 0) {
            if (k0 != i) { prow[k0] = fmaxf(acc0 + bias, 0.f); mrow[k0] = 1.f; }
            if (q1 && k1 != i) { prow[k1] = fmaxf(acc1 + bias, 0.f); mrow[k1] = 1.f; }
            if (q2 && k2 != i) { prow[k2] = fmaxf(acc2 + bias, 0.f); mrow[k2] = 1.f; }
            if (q3 && k3 != i) { prow[k3] = fmaxf(acc3 + bias, 0.f); mrow[k3] = 1.f; }
        }
    }
    // Warps whose first block is already past hi never reached the drain
    // barrier above IF hi <= lo+wid — handle by a uniform fallback: every
    // thread must hit the same number of barriers. Interior width >= 1
    // (diagonal) and streams start at lo+wid with wid<4 <= width? Not
    // guaranteed for tiny groups (width < 4): sync here for those warps.
    // NOTE: to keep barrier counts uniform, warps that skipped the loop
    // entirely execute the matching wait+barrier here.
    if (j0 >= hi) {
        if (t == 0) { /* tid0 always enters the loop: row i itself is in range */ }
        __syncthreads();
    }
    (void)j1; (void)j2; (void)j3;
}

extern "C" void kernel_launch(void* const* d_in, const int* in_sizes, int n_in,
                              void* d_out, int out_size)
{
    const float* xs    = (const float*)d_in[0];  // [1024, 256] f32
    const int*   batch = (const int*)d_in[1];    // [1024] int32 (sorted, ids in [0,32))
    const float* w     = (const float*)d_in[2];  // [256] f32
    const float* b     = (const float*)d_in[3];  // [1] f32

    float* out       = (float*)d_out;
    float* out_pred  = out;                              // [1024*1024]
    float* out_mask  = out + (size_t)NROWS * NROWS;      // [1024*1024]
    float* out_count = out + 2 * (size_t)NROWS * NROWS;  // [1]

    distmax_all<<<NROWS + 1, 128>>>(xs, batch, w, b, out_pred, out_mask, out_count);
}

// round 17
// speedup vs baseline: 1.4090x; 1.0239x over previous
#include <cuda_runtime.h>
#include <cstdint>

#define NROWS 1024
#define EMB   256

// One CTA (128 thr) per row + 1 count CTA.
// Zeros and interior are ADDRESS-DISJOINT -> no ordering wait on the path:
//   - exterior [0, lo&~3) and [(hi+3)&~3, 1024) of pred+mask rows zeroed by
//     up to 4 cp.async.bulk S2G stores from a 4KB shared zero buffer
//     (16B-aligned by construction); <=3 ragged cols per side via scalar STG
//   - interior [lo,hi) written by direct STGs (diagonal stored as 0.0)
//   - only tid0 waits on the bulk group at the very END (keeps smem alive);
//     one __syncthreads total (publish smem zeros before TMA reads them)
// Row CTA:
//   - prefetch xi/w/window/bias; ballot bounds [lo,hi) (popc thresholds)
//   - zero 4KB smem (2 STS.128/thr); sync; tid0 fence+bulk stores+commit
//   - ragged-edge scalar zeros; compute interior warp-per-j (4 streams,
//     4-way unroll, coalesced LDG.128, 5-step shfl); lane0 STGs pred/mask
//   - tid0: wait_group 0
// Count CTA (bid == NROWS): 32-bin histogram; count = sum h^2 - N.
__global__ __launch_bounds__(128) void distmax_all(
    const float* __restrict__ xs, const int* __restrict__ batch,
    const float* __restrict__ w, const float* __restrict__ bptr,
    float* __restrict__ out_pred, float* __restrict__ out_mask,
    float* __restrict__ out_count)
{
    const int t    = threadIdx.x;
    const int lane = t & 31;
    const int wid  = t >> 5;
    const int bid  = blockIdx.x;

    // ---- count CTA ----
    if (bid == NROWS) {
        __shared__ int h[32];
        if (t < 32) h[t] = 0;
        __syncthreads();
        #pragma unroll
        for (int k = 0; k < 2; k++) {
            int4 v = reinterpret_cast<const int4*>(batch)[t + k * 128];
            atomicAdd(&h[v.x], 1);
            atomicAdd(&h[v.y], 1);
            atomicAdd(&h[v.z], 1);
            atomicAdd(&h[v.w], 1);
        }
        __syncthreads();
        if (t < 32) {
            int c = h[t] * h[t];
            #pragma unroll
            for (int o = 16; o; o >>= 1) c += __shfl_xor_sync(0xffffffffu, c, o);
            if (t == 0) out_count[0] = (float)(c - NROWS);
        }
        return;
    }

    __shared__ __align__(16) float s_zero[NROWS];  // 4KB of zeros

    const int i = bid;

    // ---- prefetch independent loads ----
    int wbase = i - 64;
    if (wbase < 0) wbase = 0;
    wbase &= ~3;
    if (wbase > NROWS - 128) wbase = NROWS - 128;

    const int  bi = batch[i];
    const int4 v  = reinterpret_cast<const int4*>(batch + wbase)[lane];

    const float4* xi4 = reinterpret_cast<const float4*>(xs + (size_t)i * EMB);
    const float4* w4  = reinterpret_cast<const float4*>(w);
    const float4 xi0 = xi4[lane], xi1 = xi4[32 + lane];
    const float4 w0  = w4 [lane], w1  = w4 [32 + lane];
    const float bias = __ldg(bptr);

    // ---- zero the 4KB shared buffer: 256 float4 / 128 thr = 2 each ----
    {
        float4* s4 = reinterpret_cast<float4*>(s_zero);
        const float4 z = make_float4(0.f, 0.f, 0.f, 0.f);
        s4[t]       = z;
        s4[t + 128] = z;
    }

    // ---- ballot bounds (uniform across each warp) ----
    const int d = i - wbase;
    const unsigned m0 = __ballot_sync(0xffffffffu, v.x == bi);
    const unsigned m1 = __ballot_sync(0xffffffffu, v.y == bi);
    const unsigned m2 = __ballot_sync(0xffffffffu, v.z == bi);
    const unsigned m3 = __ballot_sync(0xffffffffu, v.w == bi);

    int nbefore = 0, nafter = 0;
    {
        const unsigned m[4] = {m0, m1, m2, m3};
        #pragma unroll
        for (int c = 0; c < 4; c++) {
            const int nlt = (d - c + 3) >> 2;
            const int nle = (d >= c) ? (((d - c) >> 2) + 1) : 0;
            const unsigned ltm = (unsigned)((1ull << nlt) - 1ull);
            const unsigned lem = (unsigned)((1ull << nle) - 1ull);
            nbefore += __popc(m[c] & ltm);
            nafter  += __popc(m[c] & ~lem);
        }
    }
    const int lo = i - nbefore;
    const int hi = i + nafter + 1;

    const int lb = lo & ~3;            // left bulk covers [0, lb)
    const int hr = (hi + 3) & ~3;      // right bulk covers [hr, NROWS)

    float* __restrict__ prow = out_pred + (size_t)i * NROWS;
    float* __restrict__ mrow = out_mask + (size_t)i * NROWS;

    // ---- publish smem zeros, then issue exterior bulk zero-stores ----
    __syncthreads();
    if (t == 0) {
        asm volatile("fence.proxy.async.shared::cta;" ::: "memory");
        const uint32_t saddr = (uint32_t)__cvta_generic_to_shared(s_zero);
        if (lb > 0) {
            const uint32_t nb = (uint32_t)lb * 4u;
            asm volatile("cp.async.bulk.global.shared::cta.bulk_group [%0], [%1], %2;"
                         :: "l"(prow), "r"(saddr), "r"(nb) : "memory");
            asm volatile("cp.async.bulk.global.shared::cta.bulk_group [%0], [%1], %2;"
                         :: "l"(mrow), "r"(saddr), "r"(nb) : "memory");
        }
        if (hr < NROWS) {
            const uint32_t nb = (uint32_t)(NROWS - hr) * 4u;
            asm volatile("cp.async.bulk.global.shared::cta.bulk_group [%0], [%1], %2;"
                         :: "l"(prow + hr), "r"(saddr), "r"(nb) : "memory");
            asm volatile("cp.async.bulk.global.shared::cta.bulk_group [%0], [%1], %2;"
                         :: "l"(mrow + hr), "r"(saddr), "r"(nb) : "memory");
        }
        asm volatile("cp.async.bulk.commit_group;" ::: "memory");
    }

    // ---- ragged-edge scalar zeros (<=3 cols per side) ----
    if (t < lo - lb)               { prow[lb + t] = 0.f; mrow[lb + t] = 0.f; }
    if (t >= 64 && t - 64 < hr - hi) {
        const int c = hi + (t - 64);
        prow[c] = 0.f; mrow[c] = 0.f;
    }

    // ---- compute interior: warp-per-j, 4 streams, 4-way unroll ----
    // Diagonal is in [lo,hi) and gets an explicit 0 store (nothing else
    // covers it). No ordering needed vs the bulk stores (disjoint ranges).
    for (int jb = lo + wid; jb < hi; jb += 16) {
        const int j0 = jb, j1 = jb + 4, j2 = jb + 8, j3 = jb + 12;
        const bool p1 = (j1 < hi), p2 = (j2 < hi), p3 = (j3 < hi);

        float acc0 = 0.f, acc1 = 0.f, acc2 = 0.f, acc3 = 0.f;
        {
            const float4* xj = reinterpret_cast<const float4*>(xs + (size_t)j0 * EMB);
            const float4 a = xj[lane], b = xj[32 + lane];
            acc0 = fmaf(fmaxf(xi0.x, a.x), w0.x, fmaf(fmaxf(xi0.y, a.y), w0.y,
                   fmaf(fmaxf(xi0.z, a.z), w0.z, fmaf(fmaxf(xi0.w, a.w), w0.w,
                   fmaf(fmaxf(xi1.x, b.x), w1.x, fmaf(fmaxf(xi1.y, b.y), w1.y,
                   fmaf(fmaxf(xi1.z, b.z), w1.z, fmaxf(xi1.w, b.w) * w1.w)))))));
        }
        if (p1) {
            const float4* xj = reinterpret_cast<const float4*>(xs + (size_t)j1 * EMB);
            const float4 a = xj[lane], b = xj[32 + lane];
            acc1 = fmaf(fmaxf(xi0.x, a.x), w0.x, fmaf(fmaxf(xi0.y, a.y), w0.y,
                   fmaf(fmaxf(xi0.z, a.z), w0.z, fmaf(fmaxf(xi0.w, a.w), w0.w,
                   fmaf(fmaxf(xi1.x, b.x), w1.x, fmaf(fmaxf(xi1.y, b.y), w1.y,
                   fmaf(fmaxf(xi1.z, b.z), w1.z, fmaxf(xi1.w, b.w) * w1.w)))))));
        }
        if (p2) {
            const float4* xj = reinterpret_cast<const float4*>(xs + (size_t)j2 * EMB);
            const float4 a = xj[lane], b = xj[32 + lane];
            acc2 = fmaf(fmaxf(xi0.x, a.x), w0.x, fmaf(fmaxf(xi0.y, a.y), w0.y,
                   fmaf(fmaxf(xi0.z, a.z), w0.z, fmaf(fmaxf(xi0.w, a.w), w0.w,
                   fmaf(fmaxf(xi1.x, b.x), w1.x, fmaf(fmaxf(xi1.y, b.y), w1.y,
                   fmaf(fmaxf(xi1.z, b.z), w1.z, fmaxf(xi1.w, b.w) * w1.w)))))));
        }
        if (p3) {
            const float4* xj = reinterpret_cast<const float4*>(xs + (size_t)j3 * EMB);
            const float4 a = xj[lane], b = xj[32 + lane];
            acc3 = fmaf(fmaxf(xi0.x, a.x), w0.x, fmaf(fmaxf(xi0.y, a.y), w0.y,
                   fmaf(fmaxf(xi0.z, a.z), w0.z, fmaf(fmaxf(xi0.w, a.w), w0.w,
                   fmaf(fmaxf(xi1.x, b.x), w1.x, fmaf(fmaxf(xi1.y, b.y), w1.y,
                   fmaf(fmaxf(xi1.z, b.z), w1.z, fmaxf(xi1.w, b.w) * w1.w)))))));
        }

        #pragma unroll
        for (int o = 16; o; o >>= 1) {
            acc0 += __shfl_xor_sync(0xffffffffu, acc0, o);
            acc1 += __shfl_xor_sync(0xffffffffu, acc1, o);
            acc2 += __shfl_xor_sync(0xffffffffu, acc2, o);
            acc3 += __shfl_xor_sync(0xffffffffu, acc3, o);
        }

        if (lane == 0) {
            prow[j0] = (j0 == i) ? 0.f : fmaxf(acc0 + bias, 0.f);
            mrow[j0] = (j0 == i) ? 0.f : 1.f;
            if (p1) { prow[j1] = (j1 == i) ? 0.f : fmaxf(acc1 + bias, 0.f);
                      mrow[j1] = (j1 == i) ? 0.f : 1.f; }
            if (p2) { prow[j2] = (j2 == i) ? 0.f : fmaxf(acc2 + bias, 0.f);
                      mrow[j2] = (j2 == i) ? 0.f : 1.f; }
            if (p3) { prow[j3] = (j3 == i) ? 0.f : fmaxf(acc3 + bias, 0.f);
                      mrow[j3] = (j3 == i) ? 0.f : 1.f; }
        }
    }

    // ---- keep smem alive until the bulk zero-stores have read it ----
    if (t == 0) {
        asm volatile("cp.async.bulk.wait_group 0;" ::: "memory");
    }
}

extern "C" void kernel_launch(void* const* d_in, const int* in_sizes, int n_in,
                              void* d_out, int out_size)
{
    const float* xs    = (const float*)d_in[0];  // [1024, 256] f32
    const int*   batch = (const int*)d_in[1];    // [1024] int32 (sorted, ids in [0,32))
    const float* w     = (const float*)d_in[2];  // [256] f32
    const float* b     = (const float*)d_in[3];  // [1] f32

    float* out       = (float*)d_out;
    float* out_pred  = out;                              // [1024*1024]
    float* out_mask  = out + (size_t)NROWS * NROWS;      // [1024*1024]
    float* out_count = out + 2 * (size_t)NROWS * NROWS;  // [1]

    distmax_all<<<NROWS + 1, 128>>>(xs, batch, w, b, out_pred, out_mask, out_count);
}